// round 1
// baseline (speedup 1.0000x reference)
#include <cuda_runtime.h>
#include <cuda_bf16.h>

#define NV      25000
#define NE      100000
#define NODE_IN 74
#define EDGE_IN 12
#define DOUT    64
#define EHID    128
#define NSTEPS  6

// Scratch (device globals; no runtime allocation allowed)
__device__ float d_h[NV * DOUT];            // node state, 6.4 MB
__device__ float d_agg[NV * DOUT];          // scatter accumulator
__device__ float d_gh[NE * EHID];           // edge hidden, 51.2 MB
__device__ float d_ew[409600000];           // per-edge 64x64 matrices, 1.64 GB

// ---------------------------------------------------------------------------
// h = relu(node_feats @ Wp + bp)   [NV,74] @ [74,64]
// one block per node, 64 threads (one per output)
// ---------------------------------------------------------------------------
__global__ void k_project(const float* __restrict__ nf,
                          const float* __restrict__ Wp,
                          const float* __restrict__ bp) {
    int v = blockIdx.x;
    int o = threadIdx.x;
    __shared__ float row[NODE_IN];
    for (int i = o; i < NODE_IN; i += DOUT) row[i] = nf[v * NODE_IN + i];
    __syncthreads();
    float acc = bp[o];
#pragma unroll
    for (int i = 0; i < NODE_IN; i++) acc += row[i] * Wp[i * DOUT + o];
    d_h[v * DOUT + o] = fmaxf(acc, 0.f);
}

// ---------------------------------------------------------------------------
// g = relu(edge_feats @ We1 + be1)  [NE,12] @ [12,128]
// one block per edge, 128 threads
// ---------------------------------------------------------------------------
__global__ void k_ehid(const float* __restrict__ ef,
                       const float* __restrict__ We1,
                       const float* __restrict__ be1) {
    int e = blockIdx.x;
    int k = threadIdx.x;
    __shared__ float row[EDGE_IN];
    if (k < EDGE_IN) row[k] = ef[e * EDGE_IN + k];
    __syncthreads();
    float acc = be1[k];
#pragma unroll
    for (int i = 0; i < EDGE_IN; i++) acc += row[i] * We1[i * EHID + k];
    d_gh[e * EHID + k] = fmaxf(acc, 0.f);
}

// ---------------------------------------------------------------------------
// ew = g @ We2 + be2   [NE,128] @ [128,4096]  -> 1.64 GB output
// Tile: 16 edges per block, 256 threads, each thread owns 4 consecutive cols
// per pass (4 passes over the 4096 cols). g tile in SMEM (broadcast reads),
// We2 read as float4 (coalesced across threads), float4 stores.
// ---------------------------------------------------------------------------
__global__ void k_ew(const float* __restrict__ We2,
                     const float* __restrict__ be2) {
    __shared__ float gs[16][EHID];                     // 8 KB
    int e0  = blockIdx.x * 16;
    int tid = threadIdx.x;
    for (int idx = tid; idx < 16 * EHID; idx += 256)
        gs[idx >> 7][idx & 127] = d_gh[e0 * EHID + idx];
    __syncthreads();

    for (int cb = 0; cb < DOUT * DOUT; cb += 1024) {
        int c = cb + tid * 4;
        float4 b4 = *reinterpret_cast<const float4*>(be2 + c);
        float ax[16], ay[16], az[16], aw[16];
#pragma unroll
        for (int e = 0; e < 16; e++) { ax[e] = b4.x; ay[e] = b4.y; az[e] = b4.z; aw[e] = b4.w; }

        for (int k = 0; k < EHID; k++) {
            float4 w = *reinterpret_cast<const float4*>(We2 + k * 4096 + c);
#pragma unroll
            for (int e = 0; e < 16; e++) {
                float gv = gs[e][k];                   // warp-uniform broadcast LDS
                ax[e] += gv * w.x;
                ay[e] += gv * w.y;
                az[e] += gv * w.z;
                aw[e] += gv * w.w;
            }
        }
#pragma unroll
        for (int e = 0; e < 16; e++) {
            float4 r = make_float4(ax[e], ay[e], az[e], aw[e]);
            *reinterpret_cast<float4*>(d_ew + (size_t)(e0 + e) * 4096 + c) = r;
        }
    }
}

// ---------------------------------------------------------------------------
// msg[e] = h[src[e]] @ ew[e]  ;  atomic scatter into d_agg[dst[e]]
// blockDim (64,4): 4 edges per block, thread x = output channel
// ---------------------------------------------------------------------------
__global__ void k_msg(const int* __restrict__ src,
                      const int* __restrict__ dst) {
    int ty = threadIdx.y;
    int e  = blockIdx.x * 4 + ty;
    int o  = threadIdx.x;
    __shared__ float hs[4][DOUT];
    int s = src[e];
    hs[ty][o] = d_h[s * DOUT + o];
    __syncthreads();

    const float* ewp = d_ew + (size_t)e * (DOUT * DOUT);
    float acc = 0.f;
#pragma unroll 8
    for (int i = 0; i < DOUT; i++)
        acc += hs[ty][i] * ewp[i * DOUT + o];          // coalesced 256B rows

    atomicAdd(&d_agg[dst[e] * DOUT + o], acc);
}

// ---------------------------------------------------------------------------
__global__ void k_zero() {
    int i = blockIdx.x * blockDim.x + threadIdx.x;
    if (i < NV * DOUT) d_agg[i] = 0.f;
}

__global__ void k_relu(const float* __restrict__ bias, float* __restrict__ out) {
    int i = blockIdx.x * blockDim.x + threadIdx.x;
    if (i < NV * DOUT) {
        float v = fmaxf(d_agg[i] + bias[i & (DOUT - 1)], 0.f);
        d_h[i] = v;
        if (out) out[i] = v;
    }
}

// ---------------------------------------------------------------------------
extern "C" void kernel_launch(void* const* d_in, const int* in_sizes, int n_in,
                              void* d_out, int out_size) {
    const float* nf   = (const float*)d_in[0];
    const float* ef   = (const float*)d_in[1];
    const int*   src  = (const int*)  d_in[2];
    const int*   dst  = (const int*)  d_in[3];
    const float* Wp   = (const float*)d_in[4];
    const float* bp   = (const float*)d_in[5];
    const float* We1  = (const float*)d_in[6];
    const float* be1  = (const float*)d_in[7];
    const float* We2  = (const float*)d_in[8];
    const float* be2  = (const float*)d_in[9];
    const float* bias = (const float*)d_in[10];
    float* out = (float*)d_out;

    k_project<<<NV, DOUT>>>(nf, Wp, bp);
    k_ehid<<<NE, EHID>>>(ef, We1, be1);
    k_ew<<<NE / 16, 256>>>(We2, be2);

    for (int s = 0; s < NSTEPS; s++) {
        k_zero<<<(NV * DOUT) / 256, 256>>>();
        k_msg<<<NE / 4, dim3(64, 4)>>>(src, dst);
        k_relu<<<(NV * DOUT) / 256, 256>>>(bias, (s == NSTEPS - 1) ? out : nullptr);
    }
}

// round 3
// speedup vs baseline: 3.2597x; 3.2597x over previous
#include <cuda_runtime.h>
#include <cuda_fp16.h>
#include <cstdint>
#include <cstddef>

#define NV      25000
#define NE      100000
#define NODE_IN 74
#define EDGE_IN 12
#define DOUT    64
#define EHID    128
#define NSTEPS  6

// Scratch (device globals; no runtime allocation allowed)
__device__ float  d_h[NV * DOUT];                    // node state
__device__ float  d_agg[NV * DOUT];                  // scatter accumulator
__device__ __half d_gh[NE * EHID];                   // edge hidden (fp16), 25.6 MB
__device__ __half d_We2t[DOUT * DOUT * EHID];        // We2 transposed [4096][128] fp16, 1 MB
__device__ __half d_ew[(size_t)NE * DOUT * DOUT];    // per-edge 64x64 matrices fp16, 819 MB

// ---------------------------------------------------------------------------
// h = relu(node_feats @ Wp + bp)   [NV,74] @ [74,64]
// ---------------------------------------------------------------------------
__global__ void k_project(const float* __restrict__ nf,
                          const float* __restrict__ Wp,
                          const float* __restrict__ bp) {
    int v = blockIdx.x;
    int o = threadIdx.x;
    __shared__ float row[NODE_IN];
    for (int i = o; i < NODE_IN; i += DOUT) row[i] = nf[v * NODE_IN + i];
    __syncthreads();
    float acc = bp[o];
#pragma unroll
    for (int i = 0; i < NODE_IN; i++) acc += row[i] * Wp[i * DOUT + o];
    d_h[v * DOUT + o] = fmaxf(acc, 0.f);
}

// ---------------------------------------------------------------------------
// g = relu(edge_feats @ We1 + be1)  [NE,12] @ [12,128]  -> fp16
// ---------------------------------------------------------------------------
__global__ void k_ehid(const float* __restrict__ ef,
                       const float* __restrict__ We1,
                       const float* __restrict__ be1) {
    int e = blockIdx.x;
    int k = threadIdx.x;
    __shared__ float row[EDGE_IN];
    if (k < EDGE_IN) row[k] = ef[e * EDGE_IN + k];
    __syncthreads();
    float acc = be1[k];
#pragma unroll
    for (int i = 0; i < EDGE_IN; i++) acc += row[i] * We1[i * EHID + k];
    d_gh[e * EHID + k] = __float2half(fmaxf(acc, 0.f));
}

// ---------------------------------------------------------------------------
// We2 [128][4096] fp32  ->  d_We2t [4096][128] fp16 (one-time, 1 MB)
// ---------------------------------------------------------------------------
__global__ void k_convW(const float* __restrict__ We2) {
    int idx = blockIdx.x * 256 + threadIdx.x;      // 524288 total
    int n = idx >> 7, k = idx & 127;
    d_We2t[idx] = __float2half(We2[k * 4096 + n]);
}

// ---------------------------------------------------------------------------
// ew = g @ We2 + be2  via fp16 HMMA (m16n8k16, fp32 accum)
// Block tile: 80 edges x 64 cols x K=128. 5 warps, warp w owns edges
// [16w,16w+16) x all 64 cols. Grid (64 n-blocks fastest, 1250 e-blocks).
// ---------------------------------------------------------------------------
__global__ __launch_bounds__(160) void k_ew(const float* __restrict__ be2) {
    __shared__ __half As[80][136];     // 21.25 KB, pad keeps rows in distinct banks
    __shared__ __half Bs[64][136];     // 17 KB
    __shared__ float  be2s[64];

    int tid  = threadIdx.x;
    int warp = tid >> 5, lane = tid & 31;
    int g = lane >> 2, tig = lane & 3;
    int e0 = blockIdx.y * 80;
    int n0 = blockIdx.x * 64;

    // stage A (g tile) and B (We2t tile), coalesced 4B copies
    for (int idx = tid; idx < 80 * 64; idx += 160) {
        int e = idx >> 6, j = idx & 63;
        *(unsigned int*)&As[e][2 * j] = *(const unsigned int*)&d_gh[(e0 + e) * EHID + 2 * j];
    }
    for (int idx = tid; idx < 64 * 64; idx += 160) {
        int r = idx >> 6, j = idx & 63;
        *(unsigned int*)&Bs[r][2 * j] = *(const unsigned int*)&d_We2t[(n0 + r) * EHID + 2 * j];
    }
    if (tid < 64) be2s[tid] = be2[n0 + tid];
    __syncthreads();

    float acc[8][4];
#pragma unroll
    for (int nt = 0; nt < 8; nt++) { acc[nt][0] = acc[nt][1] = acc[nt][2] = acc[nt][3] = 0.f; }

    int m0 = warp * 16;
#pragma unroll
    for (int kk = 0; kk < 8; kk++) {
        int kb = kk * 16 + 2 * tig;
        unsigned int a0 = *(unsigned int*)&As[m0 + g][kb];
        unsigned int a1 = *(unsigned int*)&As[m0 + g + 8][kb];
        unsigned int a2 = *(unsigned int*)&As[m0 + g][kb + 8];
        unsigned int a3 = *(unsigned int*)&As[m0 + g + 8][kb + 8];
#pragma unroll
        for (int nt = 0; nt < 8; nt++) {
            unsigned int b0 = *(unsigned int*)&Bs[nt * 8 + g][kb];
            unsigned int b1 = *(unsigned int*)&Bs[nt * 8 + g][kb + 8];
            asm volatile(
                "mma.sync.aligned.m16n8k16.row.col.f32.f16.f16.f32 "
                "{%0,%1,%2,%3}, {%4,%5,%6,%7}, {%8,%9}, {%0,%1,%2,%3};"
                : "+f"(acc[nt][0]), "+f"(acc[nt][1]), "+f"(acc[nt][2]), "+f"(acc[nt][3])
                : "r"(a0), "r"(a1), "r"(a2), "r"(a3), "r"(b0), "r"(b1));
        }
    }
    __syncthreads();   // all A/B reads done before reusing As as output staging

    __half(*Outs)[72] = reinterpret_cast<__half(*)[72]>(&As[0][0]);  // 80x72 halfs
#pragma unroll
    for (int nt = 0; nt < 8; nt++) {
        int c = nt * 8 + 2 * tig;
        __half2 v0 = __floats2half2_rn(acc[nt][0] + be2s[c], acc[nt][1] + be2s[c + 1]);
        __half2 v1 = __floats2half2_rn(acc[nt][2] + be2s[c], acc[nt][3] + be2s[c + 1]);
        *(__half2*)&Outs[m0 + g][c]     = v0;
        *(__half2*)&Outs[m0 + g + 8][c] = v1;
    }
    __syncthreads();

    // coalesced 128B-per-row stores of the 80x64 fp16 tile
    for (int idx = tid; idx < 80 * 32; idx += 160) {
        int e = idx >> 5, j = idx & 31;
        *(unsigned int*)&d_ew[(size_t)(e0 + e) * 4096 + n0 + 2 * j] =
            *(unsigned int*)&Outs[e][2 * j];
    }
}

// ---------------------------------------------------------------------------
// msg[e] = h[src[e]] @ ew[e] (fp16 weights, fp32 accum), scatter to d_agg
// blockDim (32,8): 8 edges/block, thread t owns outputs {2t, 2t+1}
// ---------------------------------------------------------------------------
__global__ void k_msg(const int* __restrict__ src,
                      const int* __restrict__ dst) {
    int t  = threadIdx.x;
    int ty = threadIdx.y;
    int e  = blockIdx.x * 8 + ty;
    __shared__ float hs[8][64];
    int s = src[e];
    hs[ty][t]      = d_h[s * 64 + t];
    hs[ty][t + 32] = d_h[s * 64 + t + 32];
    __syncwarp();                                   // warp == row ty

    const __half* ewp = d_ew + (size_t)e * 4096 + 2 * t;
    float ax = 0.f, ay = 0.f;
#pragma unroll 16
    for (int i = 0; i < 64; i++) {
        float hv = hs[ty][i];
        __half2 w = *(const __half2*)(ewp + i * 64); // 128B coalesced per warp
        float2 wf = __half22float2(w);
        ax += hv * wf.x;
        ay += hv * wf.y;
    }
    int dv = dst[e];
    atomicAdd(&d_agg[dv * 64 + 2 * t],     ax);
    atomicAdd(&d_agg[dv * 64 + 2 * t + 1], ay);
}

// ---------------------------------------------------------------------------
__global__ void k_zero() {
    int i = blockIdx.x * blockDim.x + threadIdx.x;
    if (i < NV * DOUT) d_agg[i] = 0.f;
}

__global__ void k_relu(const float* __restrict__ bias, float* __restrict__ out) {
    int i = blockIdx.x * blockDim.x + threadIdx.x;
    if (i < NV * DOUT) {
        float v = fmaxf(d_agg[i] + bias[i & (DOUT - 1)], 0.f);
        d_h[i] = v;
        if (out) out[i] = v;
    }
}

// ---------------------------------------------------------------------------
extern "C" void kernel_launch(void* const* d_in, const int* in_sizes, int n_in,
                              void* d_out, int out_size) {
    const float* nf   = (const float*)d_in[0];
    const float* ef   = (const float*)d_in[1];
    const int*   src  = (const int*)  d_in[2];
    const int*   dst  = (const int*)  d_in[3];
    const float* Wp   = (const float*)d_in[4];
    const float* bp   = (const float*)d_in[5];
    const float* We1  = (const float*)d_in[6];
    const float* be1  = (const float*)d_in[7];
    const float* We2  = (const float*)d_in[8];
    const float* be2  = (const float*)d_in[9];
    const float* bias = (const float*)d_in[10];
    float* out = (float*)d_out;

    k_project<<<NV, DOUT>>>(nf, Wp, bp);
    k_ehid<<<NE, EHID>>>(ef, We1, be1);
    k_convW<<<(DOUT * DOUT * EHID) / 256, 256>>>(We2);
    k_ew<<<dim3(64, 1250), 160>>>(be2);

    for (int s = 0; s < NSTEPS; s++) {
        k_zero<<<(NV * DOUT) / 256, 256>>>();
        k_msg<<<NE / 8, dim3(32, 8)>>>(src, dst);
        k_relu<<<(NV * DOUT) / 256, 256>>>(bias, (s == NSTEPS - 1) ? out : nullptr);
    }
}

// round 4
// speedup vs baseline: 3.2798x; 1.0062x over previous
#include <cuda_runtime.h>
#include <cuda_fp16.h>
#include <cstdint>
#include <cstddef>

#define NV      25000
#define NE      100000
#define NE_PAD  100096
#define NODE_IN 74
#define EDGE_IN 12
#define DOUT    64
#define EHID    128
#define NSTEPS  6

// Scratch (device globals; no runtime allocation allowed)
__device__ float  d_h[NV * DOUT];                     // node state
__device__ float  d_agg[NV * DOUT];                   // scatter accumulator
__device__ __half d_gh[NE_PAD * EHID];                // edge hidden (fp16), padded
__device__ __half d_We2t[DOUT * DOUT * EHID];         // We2^T [4096][128] fp16, 1 MB
__device__ __half d_ew[(size_t)NE * DOUT * DOUT];     // per-edge 64x64 fp16, 819 MB

// ---------------------------------------------------------------------------
__global__ void k_project(const float* __restrict__ nf,
                          const float* __restrict__ Wp,
                          const float* __restrict__ bp) {
    int v = blockIdx.x;
    int o = threadIdx.x;
    __shared__ float row[NODE_IN];
    for (int i = o; i < NODE_IN; i += DOUT) row[i] = nf[v * NODE_IN + i];
    __syncthreads();
    float acc = bp[o];
#pragma unroll
    for (int i = 0; i < NODE_IN; i++) acc += row[i] * Wp[i * DOUT + o];
    d_h[v * DOUT + o] = fmaxf(acc, 0.f);
}

// ---------------------------------------------------------------------------
__global__ void k_ehid(const float* __restrict__ ef,
                       const float* __restrict__ We1,
                       const float* __restrict__ be1) {
    int e = blockIdx.x;
    int k = threadIdx.x;
    __shared__ float row[EDGE_IN];
    if (k < EDGE_IN) row[k] = ef[e * EDGE_IN + k];
    __syncthreads();
    float acc = be1[k];
#pragma unroll
    for (int i = 0; i < EDGE_IN; i++) acc += row[i] * We1[i * EHID + k];
    d_gh[e * EHID + k] = __float2half(fmaxf(acc, 0.f));
}

// ---------------------------------------------------------------------------
__global__ void k_convW(const float* __restrict__ We2) {
    int idx = blockIdx.x * 256 + threadIdx.x;      // 524288 total
    int n = idx >> 7, k = idx & 127;
    d_We2t[idx] = __float2half(We2[k * 4096 + n]);
}

// ---------------------------------------------------------------------------
// ew = g @ We2 + be2 via HMMA m16n8k16 with ldmatrix fragment loads.
// Tile: 128 edges x 64 cols x K=128. 8 warps, warp w -> edges [16w,16w+16).
// Grid (64 n-blocks fastest, 782 e-blocks); last e-block stores masked.
// ---------------------------------------------------------------------------
__global__ __launch_bounds__(256) void k_ew(const float* __restrict__ be2) {
    __shared__ __half As[128][136];    // 34.8 KB (row stride 272B: LDSM conflict-free)
    __shared__ __half Bs[64][136];     // 17.4 KB
    __shared__ float  be2s[64];

    int tid  = threadIdx.x;
    int warp = tid >> 5, lane = tid & 31;
    int g = lane >> 2, tig = lane & 3;
    int e0 = blockIdx.y * 128;
    int n0 = blockIdx.x * 64;

    // stage A (g tile) and B (We2t tile): 16B coalesced copies
    for (int idx = tid; idx < 128 * 16; idx += 256) {              // 128 rows x 16 uint4
        int e = idx >> 4, j = idx & 15;
        *(uint4*)&As[e][8 * j] = *(const uint4*)&d_gh[(size_t)(e0 + e) * EHID + 8 * j];
    }
    for (int idx = tid; idx < 64 * 16; idx += 256) {
        int r = idx >> 4, j = idx & 15;
        *(uint4*)&Bs[r][8 * j] = *(const uint4*)&d_We2t[(n0 + r) * EHID + 8 * j];
    }
    if (tid < 64) be2s[tid] = be2[n0 + tid];
    __syncthreads();

    int m0 = warp * 16;
    // per-lane ldmatrix base addresses (in shared space)
    uint32_t saA = (uint32_t)__cvta_generic_to_shared(
        &As[m0 + (lane & 15)][(lane >> 4) * 8]);
    // B lanes: rows nbase + (lane>>4)*8 + (lane&7), col ((lane>>3)&1)*8
    uint32_t saB[4];
#pragma unroll
    for (int nt2 = 0; nt2 < 4; nt2++)
        saB[nt2] = (uint32_t)__cvta_generic_to_shared(
            &Bs[nt2 * 16 + ((lane >> 4) << 3) + (lane & 7)][((lane >> 3) & 1) * 8]);

    float acc[8][4];
#pragma unroll
    for (int nt = 0; nt < 8; nt++)
        acc[nt][0] = acc[nt][1] = acc[nt][2] = acc[nt][3] = 0.f;

#pragma unroll
    for (int kk = 0; kk < 8; kk++) {
        unsigned a0, a1, a2, a3;
        asm volatile("ldmatrix.sync.aligned.m8n8.x4.shared.b16 {%0,%1,%2,%3}, [%4];"
                     : "=r"(a0), "=r"(a1), "=r"(a2), "=r"(a3)
                     : "r"(saA + kk * 32));
#pragma unroll
        for (int nt2 = 0; nt2 < 4; nt2++) {
            unsigned b0, b1, b2, b3;
            asm volatile("ldmatrix.sync.aligned.m8n8.x4.shared.b16 {%0,%1,%2,%3}, [%4];"
                         : "=r"(b0), "=r"(b1), "=r"(b2), "=r"(b3)
                         : "r"(saB[nt2] + kk * 32));
            asm volatile(
                "mma.sync.aligned.m16n8k16.row.col.f32.f16.f16.f32 "
                "{%0,%1,%2,%3}, {%4,%5,%6,%7}, {%8,%9}, {%0,%1,%2,%3};"
                : "+f"(acc[2*nt2][0]), "+f"(acc[2*nt2][1]),
                  "+f"(acc[2*nt2][2]), "+f"(acc[2*nt2][3])
                : "r"(a0), "r"(a1), "r"(a2), "r"(a3), "r"(b0), "r"(b1));
            asm volatile(
                "mma.sync.aligned.m16n8k16.row.col.f32.f16.f16.f32 "
                "{%0,%1,%2,%3}, {%4,%5,%6,%7}, {%8,%9}, {%0,%1,%2,%3};"
                : "+f"(acc[2*nt2+1][0]), "+f"(acc[2*nt2+1][1]),
                  "+f"(acc[2*nt2+1][2]), "+f"(acc[2*nt2+1][3])
                : "r"(a0), "r"(a1), "r"(a2), "r"(a3), "r"(b2), "r"(b3));
        }
    }
    __syncthreads();   // all A reads done before reusing As as staging

    __half(*Outs)[72] = reinterpret_cast<__half(*)[72]>(&As[0][0]);  // 128x72, 18.4 KB
#pragma unroll
    for (int nt = 0; nt < 8; nt++) {
        int c = nt * 8 + 2 * tig;
        __half2 v0 = __floats2half2_rn(acc[nt][0] + be2s[c], acc[nt][1] + be2s[c + 1]);
        __half2 v1 = __floats2half2_rn(acc[nt][2] + be2s[c], acc[nt][3] + be2s[c + 1]);
        *(__half2*)&Outs[m0 + g][c]     = v0;
        *(__half2*)&Outs[m0 + g + 8][c] = v1;
    }
    __syncthreads();

    // 16B coalesced stores of the 128x64 fp16 tile (masked for edge tail)
    for (int idx = tid; idx < 128 * 8; idx += 256) {
        int e = idx >> 3, j = idx & 7;
        if (e0 + e < NE)
            *(uint4*)&d_ew[(size_t)(e0 + e) * 4096 + n0 + 8 * j] = *(uint4*)&Outs[e][8 * j];
    }
}

// ---------------------------------------------------------------------------
// msg[e] = h[src[e]] @ ew[e] (fp16 weights, fp32 accum), scatter to d_agg
// ---------------------------------------------------------------------------
__global__ void k_msg(const int* __restrict__ src,
                      const int* __restrict__ dst) {
    int t  = threadIdx.x;
    int ty = threadIdx.y;
    int e  = blockIdx.x * 8 + ty;
    __shared__ float hs[8][64];
    int s = src[e];
    hs[ty][t]      = d_h[s * 64 + t];
    hs[ty][t + 32] = d_h[s * 64 + t + 32];
    __syncwarp();

    const __half* ewp = d_ew + (size_t)e * 4096 + 2 * t;
    float ax = 0.f, ay = 0.f;
#pragma unroll 16
    for (int i = 0; i < 64; i++) {
        float hv = hs[ty][i];
        __half2 w = *(const __half2*)(ewp + i * 64);
        float2 wf = __half22float2(w);
        ax += hv * wf.x;
        ay += hv * wf.y;
    }
    int dv = dst[e];
    atomicAdd(&d_agg[dv * 64 + 2 * t],     ax);
    atomicAdd(&d_agg[dv * 64 + 2 * t + 1], ay);
}

// ---------------------------------------------------------------------------
__global__ void k_zero() {
    int i = blockIdx.x * blockDim.x + threadIdx.x;
    if (i < NV * DOUT) d_agg[i] = 0.f;
}

// relu + writeback, and re-zero d_agg for the next step (fuses k_zero)
__global__ void k_relu(const float* __restrict__ bias, float* __restrict__ out) {
    int i = blockIdx.x * blockDim.x + threadIdx.x;
    if (i < NV * DOUT) {
        float v = fmaxf(d_agg[i] + bias[i & (DOUT - 1)], 0.f);
        d_agg[i] = 0.f;
        d_h[i] = v;
        if (out) out[i] = v;
    }
}

// ---------------------------------------------------------------------------
extern "C" void kernel_launch(void* const* d_in, const int* in_sizes, int n_in,
                              void* d_out, int out_size) {
    const float* nf   = (const float*)d_in[0];
    const float* ef   = (const float*)d_in[1];
    const int*   src  = (const int*)  d_in[2];
    const int*   dst  = (const int*)  d_in[3];
    const float* Wp   = (const float*)d_in[4];
    const float* bp   = (const float*)d_in[5];
    const float* We1  = (const float*)d_in[6];
    const float* be1  = (const float*)d_in[7];
    const float* We2  = (const float*)d_in[8];
    const float* be2  = (const float*)d_in[9];
    const float* bias = (const float*)d_in[10];
    float* out = (float*)d_out;

    k_project<<<NV, DOUT>>>(nf, Wp, bp);
    k_ehid<<<NE, EHID>>>(ef, We1, be1);
    k_convW<<<(DOUT * DOUT * EHID) / 256, 256>>>(We2);
    k_ew<<<dim3(64, 782), 256>>>(be2);

    k_zero<<<(NV * DOUT) / 256, 256>>>();
    for (int s = 0; s < NSTEPS; s++) {
        k_msg<<<NE / 8, dim3(32, 8)>>>(src, dst);
        k_relu<<<(NV * DOUT) / 256, 256>>>(bias, (s == NSTEPS - 1) ? out : nullptr);
    }
}

// round 5
// speedup vs baseline: 3.5392x; 1.0791x over previous
#include <cuda_runtime.h>
#include <cuda_fp16.h>
#include <cstdint>
#include <cstddef>

#define NV      25000
#define NE      100000
#define NE_PAD  100096
#define NODE_IN 74
#define EDGE_IN 12
#define DOUT    64
#define EHID    128
#define NSTEPS  6

// Scratch (device globals; no runtime allocation allowed)
__device__ float  d_h[NV * DOUT];                     // node state
__device__ float  d_agg[NV * DOUT];                   // scatter accumulator
__device__ __half d_gh[NE_PAD * EHID];                // edge hidden (fp16), padded
__device__ __half d_We2t[DOUT * DOUT * EHID];         // We2^T [4096][128] fp16, 1 MB
__device__ __half d_ew[(size_t)NE * DOUT * DOUT];     // per-edge 64x64 fp16, 819 MB

// ---------------------------------------------------------------------------
__global__ void k_project(const float* __restrict__ nf,
                          const float* __restrict__ Wp,
                          const float* __restrict__ bp) {
    int v = blockIdx.x;
    int o = threadIdx.x;
    __shared__ float row[NODE_IN];
    for (int i = o; i < NODE_IN; i += DOUT) row[i] = nf[v * NODE_IN + i];
    __syncthreads();
    float acc = bp[o];
#pragma unroll
    for (int i = 0; i < NODE_IN; i++) acc += row[i] * Wp[i * DOUT + o];
    d_h[v * DOUT + o] = fmaxf(acc, 0.f);
}

// ---------------------------------------------------------------------------
__global__ void k_ehid(const float* __restrict__ ef,
                       const float* __restrict__ We1,
                       const float* __restrict__ be1) {
    int e = blockIdx.x;
    int k = threadIdx.x;
    __shared__ float row[EDGE_IN];
    if (k < EDGE_IN) row[k] = ef[e * EDGE_IN + k];
    __syncthreads();
    float acc = be1[k];
#pragma unroll
    for (int i = 0; i < EDGE_IN; i++) acc += row[i] * We1[i * EHID + k];
    d_gh[e * EHID + k] = __float2half(fmaxf(acc, 0.f));
}

// ---------------------------------------------------------------------------
__global__ void k_convW(const float* __restrict__ We2) {
    int idx = blockIdx.x * 256 + threadIdx.x;      // 524288 total
    int n = idx >> 7, k = idx & 127;
    d_We2t[idx] = __float2half(We2[k * 4096 + n]);
}

// ---------------------------------------------------------------------------
// ew = g @ We2 + be2 via HMMA m16n8k16, ldmatrix feeds, 64x64 warp tiles.
// Block tile: 128 edges x 128 cols, K=128 in 2 chunks of 64.
// 4 warps in 2x2: warp tile 64 edges x 64 cols (acc = 128 fp32 regs).
// Grid (32 n-blocks fastest, 782 e-blocks); edge-tail masked on store.
// ---------------------------------------------------------------------------
__global__ __launch_bounds__(128) void k_ew(const float* __restrict__ be2) {
    // A tile = sb[0 .. 128*72), B tile = sb[128*72 .. 2*128*72). 36.9 KB.
    // Row stride 72 halfs (144B): 144 mod 128 = 16 -> LDSM conflict-free.
    __shared__ __align__(16) __half sb[2 * 128 * 72];
    __shared__ float be2s[128];

    int tid  = threadIdx.x;
    int warp = tid >> 5, lane = tid & 31;
    int g = lane >> 2, tig = lane & 3;
    int wm = (warp >> 1) * 64;          // warp edge offset within tile
    int wn = (warp & 1) * 64;           // warp col offset within tile
    int e0 = blockIdx.y * 128;
    int n0 = blockIdx.x * 128;

    be2s[tid] = be2[n0 + tid];

    // ldmatrix shared addresses (byte offsets advance by kk*32 inside loop)
    uint32_t saA[4], saB[4];
#pragma unroll
    for (int mt = 0; mt < 4; mt++)
        saA[mt] = (uint32_t)__cvta_generic_to_shared(
            &sb[(wm + mt * 16 + (lane & 15)) * 72 + (lane >> 4) * 8]);
#pragma unroll
    for (int ntt = 0; ntt < 4; ntt++)
        saB[ntt] = (uint32_t)__cvta_generic_to_shared(
            &sb[128 * 72 + (wn + ntt * 16 + ((lane >> 4) << 3) + (lane & 7)) * 72 +
                ((lane >> 3) & 1) * 8]);

    float acc[4][8][4];
#pragma unroll
    for (int mt = 0; mt < 4; mt++)
#pragma unroll
        for (int nt = 0; nt < 8; nt++)
            acc[mt][nt][0] = acc[mt][nt][1] = acc[mt][nt][2] = acc[mt][nt][3] = 0.f;

#pragma unroll
    for (int kc = 0; kc < 2; kc++) {
        if (kc) __syncthreads();
        // stage A rows (edges) and B rows (output cols), 16B coalesced
        for (int idx = tid; idx < 128 * 8; idx += 128) {
            int r = idx >> 3, j = idx & 7;
            *(uint4*)&sb[r * 72 + 8 * j] =
                *(const uint4*)&d_gh[(size_t)(e0 + r) * EHID + kc * 64 + 8 * j];
        }
        for (int idx = tid; idx < 128 * 8; idx += 128) {
            int r = idx >> 3, j = idx & 7;
            *(uint4*)&sb[128 * 72 + r * 72 + 8 * j] =
                *(const uint4*)&d_We2t[(size_t)(n0 + r) * EHID + kc * 64 + 8 * j];
        }
        __syncthreads();

#pragma unroll
        for (int kk = 0; kk < 4; kk++) {
            unsigned a[4][4];
#pragma unroll
            for (int mt = 0; mt < 4; mt++)
                asm volatile("ldmatrix.sync.aligned.m8n8.x4.shared.b16 {%0,%1,%2,%3}, [%4];"
                             : "=r"(a[mt][0]), "=r"(a[mt][1]), "=r"(a[mt][2]), "=r"(a[mt][3])
                             : "r"(saA[mt] + kk * 32));
#pragma unroll
            for (int ntt = 0; ntt < 4; ntt++) {
                unsigned b0, b1, b2, b3;
                asm volatile("ldmatrix.sync.aligned.m8n8.x4.shared.b16 {%0,%1,%2,%3}, [%4];"
                             : "=r"(b0), "=r"(b1), "=r"(b2), "=r"(b3)
                             : "r"(saB[ntt] + kk * 32));
#pragma unroll
                for (int mt = 0; mt < 4; mt++) {
                    asm volatile(
                        "mma.sync.aligned.m16n8k16.row.col.f32.f16.f16.f32 "
                        "{%0,%1,%2,%3}, {%4,%5,%6,%7}, {%8,%9}, {%0,%1,%2,%3};"
                        : "+f"(acc[mt][2*ntt][0]), "+f"(acc[mt][2*ntt][1]),
                          "+f"(acc[mt][2*ntt][2]), "+f"(acc[mt][2*ntt][3])
                        : "r"(a[mt][0]), "r"(a[mt][1]), "r"(a[mt][2]), "r"(a[mt][3]),
                          "r"(b0), "r"(b1));
                    asm volatile(
                        "mma.sync.aligned.m16n8k16.row.col.f32.f16.f16.f32 "
                        "{%0,%1,%2,%3}, {%4,%5,%6,%7}, {%8,%9}, {%0,%1,%2,%3};"
                        : "+f"(acc[mt][2*ntt+1][0]), "+f"(acc[mt][2*ntt+1][1]),
                          "+f"(acc[mt][2*ntt+1][2]), "+f"(acc[mt][2*ntt+1][3])
                        : "r"(a[mt][0]), "r"(a[mt][1]), "r"(a[mt][2]), "r"(a[mt][3]),
                          "r"(b2), "r"(b3));
                }
            }
        }
    }
    __syncthreads();   // all tile reads done; reuse sb as output staging

    __half(*Outs)[136] = reinterpret_cast<__half(*)[136]>(&sb[0]);  // 128x136, 34.8 KB
#pragma unroll
    for (int mt = 0; mt < 4; mt++)
#pragma unroll
        for (int nt = 0; nt < 8; nt++) {
            int r = wm + mt * 16 + g;
            int c = wn + nt * 8 + 2 * tig;
            __half2 v0 = __floats2half2_rn(acc[mt][nt][0] + be2s[c],
                                           acc[mt][nt][1] + be2s[c + 1]);
            __half2 v1 = __floats2half2_rn(acc[mt][nt][2] + be2s[c],
                                           acc[mt][nt][3] + be2s[c + 1]);
            *(__half2*)&Outs[r][c]     = v0;
            *(__half2*)&Outs[r + 8][c] = v1;
        }
    __syncthreads();

    // 16B coalesced stores of the 128x128 fp16 tile (masked edge tail)
    for (int idx = tid; idx < 128 * 16; idx += 128) {
        int e = idx >> 4, j = idx & 15;
        if (e0 + e < NE)
            *(uint4*)&d_ew[(size_t)(e0 + e) * 4096 + n0 + 8 * j] = *(uint4*)&Outs[e][8 * j];
    }
}

// ---------------------------------------------------------------------------
// msg[e] = h[src[e]] @ ew[e] (fp16 weights, fp32 accum), scatter to d_agg
// ---------------------------------------------------------------------------
__global__ void k_msg(const int* __restrict__ src,
                      const int* __restrict__ dst) {
    int t  = threadIdx.x;
    int ty = threadIdx.y;
    int e  = blockIdx.x * 8 + ty;
    __shared__ float hs[8][64];
    int s = src[e];
    hs[ty][t]      = d_h[s * 64 + t];
    hs[ty][t + 32] = d_h[s * 64 + t + 32];
    __syncwarp();

    const __half* ewp = d_ew + (size_t)e * 4096 + 2 * t;
    float ax = 0.f, ay = 0.f;
#pragma unroll 16
    for (int i = 0; i < 64; i++) {
        float hv = hs[ty][i];
        __half2 w = *(const __half2*)(ewp + i * 64);
        float2 wf = __half22float2(w);
        ax += hv * wf.x;
        ay += hv * wf.y;
    }
    int dv = dst[e];
    atomicAdd(&d_agg[dv * 64 + 2 * t],     ax);
    atomicAdd(&d_agg[dv * 64 + 2 * t + 1], ay);
}

// ---------------------------------------------------------------------------
__global__ void k_zero() {
    int i = blockIdx.x * blockDim.x + threadIdx.x;
    if (i < NV * DOUT) d_agg[i] = 0.f;
}

// relu + writeback, and re-zero d_agg for the next step (fuses k_zero)
__global__ void k_relu(const float* __restrict__ bias, float* __restrict__ out) {
    int i = blockIdx.x * blockDim.x + threadIdx.x;
    if (i < NV * DOUT) {
        float v = fmaxf(d_agg[i] + bias[i & (DOUT - 1)], 0.f);
        d_agg[i] = 0.f;
        d_h[i] = v;
        if (out) out[i] = v;
    }
}

// ---------------------------------------------------------------------------
extern "C" void kernel_launch(void* const* d_in, const int* in_sizes, int n_in,
                              void* d_out, int out_size) {
    const float* nf   = (const float*)d_in[0];
    const float* ef   = (const float*)d_in[1];
    const int*   src  = (const int*)  d_in[2];
    const int*   dst  = (const int*)  d_in[3];
    const float* Wp   = (const float*)d_in[4];
    const float* bp   = (const float*)d_in[5];
    const float* We1  = (const float*)d_in[6];
    const float* be1  = (const float*)d_in[7];
    const float* We2  = (const float*)d_in[8];
    const float* be2  = (const float*)d_in[9];
    const float* bias = (const float*)d_in[10];
    float* out = (float*)d_out;

    k_project<<<NV, DOUT>>>(nf, Wp, bp);
    k_ehid<<<NE, EHID>>>(ef, We1, be1);
    k_convW<<<(DOUT * DOUT * EHID) / 256, 256>>>(We2);
    k_ew<<<dim3(32, 782), 128>>>(be2);

    k_zero<<<(NV * DOUT) / 256, 256>>>();
    for (int s = 0; s < NSTEPS; s++) {
        k_msg<<<NE / 8, dim3(32, 8)>>>(src, dst);
        k_relu<<<(NV * DOUT) / 256, 256>>>(bias, (s == NSTEPS - 1) ? out : nullptr);
    }
}

// round 6
// speedup vs baseline: 4.0612x; 1.1475x over previous
#include <cuda_runtime.h>
#include <cuda_fp16.h>
#include <cstdint>
#include <cstddef>

#define NV      25000
#define NE      100000
#define NE_PAD  100096
#define NODE_IN 74
#define EDGE_IN 12
#define DOUT    64
#define EHID    128
#define NSTEPS  6

#define EW_SMEM (2 * 128 * 136 * 2 + 512)   // A + B tiles (fp16) + be2s

// Scratch (device globals; no runtime allocation allowed)
__device__ float  d_h[NV * DOUT];                     // node state
__device__ float  d_agg[NV * DOUT];                   // scatter accumulator
__device__ __half d_gh[NE_PAD * EHID];                // edge hidden (fp16), padded
__device__ __half d_We2t[DOUT * DOUT * EHID];         // We2^T [4096][128] fp16, 1 MB
__device__ __half d_ew[(size_t)NE * DOUT * DOUT];     // per-edge 64x64 fp16, 819 MB

// ---------------------------------------------------------------------------
__global__ void k_project(const float* __restrict__ nf,
                          const float* __restrict__ Wp,
                          const float* __restrict__ bp) {
    int v = blockIdx.x;
    int o = threadIdx.x;
    __shared__ float row[NODE_IN];
    for (int i = o; i < NODE_IN; i += DOUT) row[i] = nf[v * NODE_IN + i];
    __syncthreads();
    float acc = bp[o];
#pragma unroll
    for (int i = 0; i < NODE_IN; i++) acc += row[i] * Wp[i * DOUT + o];
    d_h[v * DOUT + o] = fmaxf(acc, 0.f);
}

// ---------------------------------------------------------------------------
__global__ void k_ehid(const float* __restrict__ ef,
                       const float* __restrict__ We1,
                       const float* __restrict__ be1) {
    int e = blockIdx.x;
    int k = threadIdx.x;
    __shared__ float row[EDGE_IN];
    if (k < EDGE_IN) row[k] = ef[e * EDGE_IN + k];
    __syncthreads();
    float acc = be1[k];
#pragma unroll
    for (int i = 0; i < EDGE_IN; i++) acc += row[i] * We1[i * EHID + k];
    d_gh[e * EHID + k] = __float2half(fmaxf(acc, 0.f));
}

// ---------------------------------------------------------------------------
__global__ void k_convW(const float* __restrict__ We2) {
    int idx = blockIdx.x * 256 + threadIdx.x;      // 524288 total
    int n = idx >> 7, k = idx & 127;
    d_We2t[idx] = __float2half(We2[k * 4096 + n]);
}

// ---------------------------------------------------------------------------
// ew = g @ We2 + be2 via HMMA m16n8k16, ldmatrix feeds, 64x64 warp tiles.
// Block tile: 128 edges x 128 cols, FULL K=128 resident in dynamic smem
// (70 KB -> 3 CTAs/SM). One sync between load and 8 MMA k-steps.
// ---------------------------------------------------------------------------
__global__ __launch_bounds__(128) void k_ew(const float* __restrict__ be2) {
    extern __shared__ __align__(16) __half sb[];
    __half* As = sb;                       // 128 x 136 halfs (stride 272B, LDSM-safe)
    __half* Bs = sb + 128 * 136;           // 128 x 136 halfs
    float* be2s = (float*)(sb + 2 * 128 * 136);

    int tid  = threadIdx.x;
    int warp = tid >> 5, lane = tid & 31;
    int g = lane >> 2, tig = lane & 3;
    int wm = (warp >> 1) * 64;             // warp edge offset
    int wn = (warp & 1) * 64;              // warp col offset
    int e0 = blockIdx.y * 128;
    int n0 = blockIdx.x * 128;

    be2s[tid] = be2[n0 + tid];

    // stage full-K A and B tiles, 16B coalesced
    for (int idx = tid; idx < 128 * 16; idx += 128) {
        int r = idx >> 4, j = idx & 15;
        *(uint4*)&As[r * 136 + 8 * j] =
            *(const uint4*)&d_gh[(size_t)(e0 + r) * EHID + 8 * j];
        *(uint4*)&Bs[r * 136 + 8 * j] =
            *(const uint4*)&d_We2t[(size_t)(n0 + r) * EHID + 8 * j];
    }

    uint32_t saA[4], saB[4];
#pragma unroll
    for (int mt = 0; mt < 4; mt++)
        saA[mt] = (uint32_t)__cvta_generic_to_shared(
            &As[(wm + mt * 16 + (lane & 15)) * 136 + (lane >> 4) * 8]);
#pragma unroll
    for (int ntt = 0; ntt < 4; ntt++)
        saB[ntt] = (uint32_t)__cvta_generic_to_shared(
            &Bs[(wn + ntt * 16 + ((lane >> 4) << 3) + (lane & 7)) * 136 +
                ((lane >> 3) & 1) * 8]);

    float acc[4][8][4];
#pragma unroll
    for (int mt = 0; mt < 4; mt++)
#pragma unroll
        for (int nt = 0; nt < 8; nt++)
            acc[mt][nt][0] = acc[mt][nt][1] = acc[mt][nt][2] = acc[mt][nt][3] = 0.f;

    __syncthreads();

#pragma unroll
    for (int kk = 0; kk < 8; kk++) {
        unsigned a[4][4];
#pragma unroll
        for (int mt = 0; mt < 4; mt++)
            asm volatile("ldmatrix.sync.aligned.m8n8.x4.shared.b16 {%0,%1,%2,%3}, [%4];"
                         : "=r"(a[mt][0]), "=r"(a[mt][1]), "=r"(a[mt][2]), "=r"(a[mt][3])
                         : "r"(saA[mt] + kk * 32));
#pragma unroll
        for (int ntt = 0; ntt < 4; ntt++) {
            unsigned b0, b1, b2, b3;
            asm volatile("ldmatrix.sync.aligned.m8n8.x4.shared.b16 {%0,%1,%2,%3}, [%4];"
                         : "=r"(b0), "=r"(b1), "=r"(b2), "=r"(b3)
                         : "r"(saB[ntt] + kk * 32));
#pragma unroll
            for (int mt = 0; mt < 4; mt++) {
                asm volatile(
                    "mma.sync.aligned.m16n8k16.row.col.f32.f16.f16.f32 "
                    "{%0,%1,%2,%3}, {%4,%5,%6,%7}, {%8,%9}, {%0,%1,%2,%3};"
                    : "+f"(acc[mt][2*ntt][0]), "+f"(acc[mt][2*ntt][1]),
                      "+f"(acc[mt][2*ntt][2]), "+f"(acc[mt][2*ntt][3])
                    : "r"(a[mt][0]), "r"(a[mt][1]), "r"(a[mt][2]), "r"(a[mt][3]),
                      "r"(b0), "r"(b1));
                asm volatile(
                    "mma.sync.aligned.m16n8k16.row.col.f32.f16.f16.f32 "
                    "{%0,%1,%2,%3}, {%4,%5,%6,%7}, {%8,%9}, {%0,%1,%2,%3};"
                    : "+f"(acc[mt][2*ntt+1][0]), "+f"(acc[mt][2*ntt+1][1]),
                      "+f"(acc[mt][2*ntt+1][2]), "+f"(acc[mt][2*ntt+1][3])
                    : "r"(a[mt][0]), "r"(a[mt][1]), "r"(a[mt][2]), "r"(a[mt][3]),
                      "r"(b2), "r"(b3));
            }
        }
    }
    __syncthreads();   // tile reads done; reuse As region as output staging

    __half* Outs = As;                     // 128 x 136
#pragma unroll
    for (int mt = 0; mt < 4; mt++)
#pragma unroll
        for (int nt = 0; nt < 8; nt++) {
            int r = wm + mt * 16 + g;
            int c = wn + nt * 8 + 2 * tig;
            __half2 v0 = __floats2half2_rn(acc[mt][nt][0] + be2s[c],
                                           acc[mt][nt][1] + be2s[c + 1]);
            __half2 v1 = __floats2half2_rn(acc[mt][nt][2] + be2s[c],
                                           acc[mt][nt][3] + be2s[c + 1]);
            *(__half2*)&Outs[r * 136 + c]       = v0;
            *(__half2*)&Outs[(r + 8) * 136 + c] = v1;
        }
    __syncthreads();

    // 16B coalesced stores of the 128x128 fp16 tile (masked edge tail)
    for (int idx = tid; idx < 128 * 16; idx += 128) {
        int e = idx >> 4, j = idx & 15;
        if (e0 + e < NE)
            *(uint4*)&d_ew[(size_t)(e0 + e) * 4096 + n0 + 8 * j] =
                *(uint4*)&Outs[e * 136 + 8 * j];
    }
}

// ---------------------------------------------------------------------------
// msg[e] = h[src[e]] @ ew[e]; skip rows where h value is exactly 0 (ReLU
// sparsity, ~50%). hv is warp-uniform -> whole 128B ew row read is skipped.
// ---------------------------------------------------------------------------
__global__ void k_msg(const int* __restrict__ src,
                      const int* __restrict__ dst) {
    int t  = threadIdx.x;
    int ty = threadIdx.y;
    int e  = blockIdx.x * 8 + ty;
    __shared__ float hs[8][64];
    int s = src[e];
    hs[ty][t]      = d_h[s * 64 + t];
    hs[ty][t + 32] = d_h[s * 64 + t + 32];
    __syncwarp();

    const __half* ewp = d_ew + (size_t)e * 4096 + 2 * t;
    float ax = 0.f, ay = 0.f;
#pragma unroll 8
    for (int i = 0; i < 64; i++) {
        float hv = hs[ty][i];
        if (hv > 0.f) {                              // warp-uniform branch
            __half2 w = *(const __half2*)(ewp + i * 64);
            float2 wf = __half22float2(w);
            ax += hv * wf.x;
            ay += hv * wf.y;
        }
    }
    int dv = dst[e];
    atomicAdd(&d_agg[dv * 64 + 2 * t],     ax);
    atomicAdd(&d_agg[dv * 64 + 2 * t + 1], ay);
}

// ---------------------------------------------------------------------------
__global__ void k_zero() {
    int i = blockIdx.x * blockDim.x + threadIdx.x;
    if (i < NV * DOUT) d_agg[i] = 0.f;
}

// relu + writeback, and re-zero d_agg for the next step (fuses k_zero)
__global__ void k_relu(const float* __restrict__ bias, float* __restrict__ out) {
    int i = blockIdx.x * blockDim.x + threadIdx.x;
    if (i < NV * DOUT) {
        float v = fmaxf(d_agg[i] + bias[i & (DOUT - 1)], 0.f);
        d_agg[i] = 0.f;
        d_h[i] = v;
        if (out) out[i] = v;
    }
}

// ---------------------------------------------------------------------------
extern "C" void kernel_launch(void* const* d_in, const int* in_sizes, int n_in,
                              void* d_out, int out_size) {
    const float* nf   = (const float*)d_in[0];
    const float* ef   = (const float*)d_in[1];
    const int*   src  = (const int*)  d_in[2];
    const int*   dst  = (const int*)  d_in[3];
    const float* Wp   = (const float*)d_in[4];
    const float* bp   = (const float*)d_in[5];
    const float* We1  = (const float*)d_in[6];
    const float* be1  = (const float*)d_in[7];
    const float* We2  = (const float*)d_in[8];
    const float* be2  = (const float*)d_in[9];
    const float* bias = (const float*)d_in[10];
    float* out = (float*)d_out;

    cudaFuncSetAttribute(k_ew, cudaFuncAttributeMaxDynamicSharedMemorySize, EW_SMEM);

    k_project<<<NV, DOUT>>>(nf, Wp, bp);
    k_ehid<<<NE, EHID>>>(ef, We1, be1);
    k_convW<<<(DOUT * DOUT * EHID) / 256, 256>>>(We2);
    k_ew<<<dim3(32, 782), 128, EW_SMEM>>>(be2);

    k_zero<<<(NV * DOUT) / 256, 256>>>();
    for (int s = 0; s < NSTEPS; s++) {
        k_msg<<<NE / 8, dim3(32, 8)>>>(src, dst);
        k_relu<<<(NV * DOUT) / 256, 256>>>(bias, (s == NSTEPS - 1) ? out : nullptr);
    }
}

// round 7
// speedup vs baseline: 4.7610x; 1.1723x over previous
#include <cuda_runtime.h>
#include <cuda_fp16.h>
#include <cstdint>
#include <cstddef>

#define NV      25000
#define NE      100000
#define NE_PAD  100096
#define NODE_IN 74
#define EDGE_IN 12
#define DOUT    64
#define EHID    128
#define NSTEPS  6

// Scratch (device globals; no runtime allocation allowed)
__device__ float  d_h[NV * DOUT];                     // node state
__device__ float  d_agg[NV * DOUT];                   // scatter accumulator
__device__ __half d_gh[NE_PAD * EHID];                // edge hidden (fp16), padded
__device__ __half d_We2t[DOUT * DOUT * EHID];         // We2^T [4096][128] fp16, 1 MB
__device__ __half d_ew[(size_t)NE * DOUT * DOUT];     // per-edge 64x64 fp16, 819 MB

// ---------------------------------------------------------------------------
__global__ void k_project(const float* __restrict__ nf,
                          const float* __restrict__ Wp,
                          const float* __restrict__ bp) {
    int v = blockIdx.x;
    int o = threadIdx.x;
    __shared__ float row[NODE_IN];
    for (int i = o; i < NODE_IN; i += DOUT) row[i] = nf[v * NODE_IN + i];
    __syncthreads();
    float acc = bp[o];
#pragma unroll
    for (int i = 0; i < NODE_IN; i++) acc += row[i] * Wp[i * DOUT + o];
    d_h[v * DOUT + o] = fmaxf(acc, 0.f);
}

// ---------------------------------------------------------------------------
__global__ void k_ehid(const float* __restrict__ ef,
                       const float* __restrict__ We1,
                       const float* __restrict__ be1) {
    int e = blockIdx.x;
    int k = threadIdx.x;
    __shared__ float row[EDGE_IN];
    if (k < EDGE_IN) row[k] = ef[e * EDGE_IN + k];
    __syncthreads();
    float acc = be1[k];
#pragma unroll
    for (int i = 0; i < EDGE_IN; i++) acc += row[i] * We1[i * EHID + k];
    d_gh[e * EHID + k] = __float2half(fmaxf(acc, 0.f));
}

// ---------------------------------------------------------------------------
__global__ void k_convW(const float* __restrict__ We2) {
    int idx = blockIdx.x * 256 + threadIdx.x;      // 524288 total
    int n = idx >> 7, k = idx & 127;
    d_We2t[idx] = __float2half(We2[k * 4096 + n]);
}

// ---------------------------------------------------------------------------
// ew = g @ We2 + be2. HMMA m16n8k16, ldmatrix feeds, 64x64 warp tiles.
// Block tile 128 edges x 128 cols. K = 4 chunks of 32, double-buffered
// with cp.async so chunk kc+2 streams while chunk kc computes.
// Static smem 41.5 KB; __launch_bounds__(128,3) forces 3 CTAs/SM.
// ---------------------------------------------------------------------------
#define CH_STRIDE 40                       // halfs per row in a chunk buffer (80B)
__shared__ __align__(16) extern __half dummy_decl[];  // (unused; keep static below)

__device__ __forceinline__ void cp16(uint32_t smem_dst, const void* gmem_src) {
    asm volatile("cp.async.cg.shared.global [%0], [%1], 16;\n"
                 :: "r"(smem_dst), "l"(gmem_src));
}

__global__ __launch_bounds__(128, 3) void k_ew(const float* __restrict__ be2) {
    // [stage][A=0/B=1][128 rows x 40 halfs]
    __shared__ __align__(16) __half sb[2][2][128 * CH_STRIDE];
    __shared__ float be2s[128];

    int tid  = threadIdx.x;
    int warp = tid >> 5, lane = tid & 31;
    int g = lane >> 2, tig = lane & 3;
    int wm = (warp >> 1) * 64;             // warp edge offset
    int wn = (warp & 1) * 64;              // warp col offset
    int e0 = blockIdx.y * 128;
    int n0 = blockIdx.x * 128;

    be2s[tid] = be2[n0 + tid];

    // ---- async chunk loader: chunk kc (K cols [32kc,32kc+32)) into stage st
    auto load_chunk = [&](int kc, int st) {
#pragma unroll
        for (int it = 0; it < 4; it++) {
            int idx = tid + it * 128;              // 0..511
            int r = idx >> 2, j = idx & 3;
            cp16((uint32_t)__cvta_generic_to_shared(&sb[st][0][r * CH_STRIDE + 8 * j]),
                 &d_gh[(size_t)(e0 + r) * EHID + kc * 32 + 8 * j]);
            cp16((uint32_t)__cvta_generic_to_shared(&sb[st][1][r * CH_STRIDE + 8 * j]),
                 &d_We2t[(size_t)(n0 + r) * EHID + kc * 32 + 8 * j]);
        }
        asm volatile("cp.async.commit_group;\n");
    };

    load_chunk(0, 0);
    load_chunk(1, 1);

    // per-lane ldmatrix offsets within a stage buffer (bytes)
    uint32_t offA[4], offB[4];
#pragma unroll
    for (int mt = 0; mt < 4; mt++)
        offA[mt] = (uint32_t)((wm + mt * 16 + (lane & 15)) * CH_STRIDE * 2 +
                              (lane >> 4) * 16);
#pragma unroll
    for (int ntt = 0; ntt < 4; ntt++)
        offB[ntt] = (uint32_t)((wn + ntt * 16 + ((lane >> 4) << 3) + (lane & 7)) *
                               CH_STRIDE * 2 + ((lane >> 3) & 1) * 16);

    float acc[4][8][4];
#pragma unroll
    for (int mt = 0; mt < 4; mt++)
#pragma unroll
        for (int nt = 0; nt < 8; nt++)
            acc[mt][nt][0] = acc[mt][nt][1] = acc[mt][nt][2] = acc[mt][nt][3] = 0.f;

#pragma unroll
    for (int kc = 0; kc < 4; kc++) {
        if (kc < 3) asm volatile("cp.async.wait_group 1;\n");
        else        asm volatile("cp.async.wait_group 0;\n");
        __syncthreads();

        int st = kc & 1;
        uint32_t baseA = (uint32_t)__cvta_generic_to_shared(&sb[st][0][0]);
        uint32_t baseB = (uint32_t)__cvta_generic_to_shared(&sb[st][1][0]);

#pragma unroll
        for (int kk = 0; kk < 2; kk++) {
            unsigned a[4][4];
#pragma unroll
            for (int mt = 0; mt < 4; mt++)
                asm volatile("ldmatrix.sync.aligned.m8n8.x4.shared.b16 {%0,%1,%2,%3}, [%4];"
                             : "=r"(a[mt][0]), "=r"(a[mt][1]), "=r"(a[mt][2]), "=r"(a[mt][3])
                             : "r"(baseA + offA[mt] + kk * 32));
#pragma unroll
            for (int ntt = 0; ntt < 4; ntt++) {
                unsigned b0, b1, b2, b3;
                asm volatile("ldmatrix.sync.aligned.m8n8.x4.shared.b16 {%0,%1,%2,%3}, [%4];"
                             : "=r"(b0), "=r"(b1), "=r"(b2), "=r"(b3)
                             : "r"(baseB + offB[ntt] + kk * 32));
#pragma unroll
                for (int mt = 0; mt < 4; mt++) {
                    asm volatile(
                        "mma.sync.aligned.m16n8k16.row.col.f32.f16.f16.f32 "
                        "{%0,%1,%2,%3}, {%4,%5,%6,%7}, {%8,%9}, {%0,%1,%2,%3};"
                        : "+f"(acc[mt][2*ntt][0]), "+f"(acc[mt][2*ntt][1]),
                          "+f"(acc[mt][2*ntt][2]), "+f"(acc[mt][2*ntt][3])
                        : "r"(a[mt][0]), "r"(a[mt][1]), "r"(a[mt][2]), "r"(a[mt][3]),
                          "r"(b0), "r"(b1));
                    asm volatile(
                        "mma.sync.aligned.m16n8k16.row.col.f32.f16.f16.f32 "
                        "{%0,%1,%2,%3}, {%4,%5,%6,%7}, {%8,%9}, {%0,%1,%2,%3};"
                        : "+f"(acc[mt][2*ntt+1][0]), "+f"(acc[mt][2*ntt+1][1]),
                          "+f"(acc[mt][2*ntt+1][2]), "+f"(acc[mt][2*ntt+1][3])
                        : "r"(a[mt][0]), "r"(a[mt][1]), "r"(a[mt][2]), "r"(a[mt][3]),
                          "r"(b2), "r"(b3));
                }
            }
        }
        __syncthreads();                    // buffer free before next fill
        if (kc < 2) load_chunk(kc + 2, st);
    }

    // epilogue: stage through smem for coalesced 16B stores
    __half(*Outs)[136] = reinterpret_cast<__half(*)[136]>(&sb[0][0][0]);  // 128x136
#pragma unroll
    for (int mt = 0; mt < 4; mt++)
#pragma unroll
        for (int nt = 0; nt < 8; nt++) {
            int r = wm + mt * 16 + g;
            int c = wn + nt * 8 + 2 * tig;
            __half2 v0 = __floats2half2_rn(acc[mt][nt][0] + be2s[c],
                                           acc[mt][nt][1] + be2s[c + 1]);
            __half2 v1 = __floats2half2_rn(acc[mt][nt][2] + be2s[c],
                                           acc[mt][nt][3] + be2s[c + 1]);
            *(__half2*)&Outs[r][c]     = v0;
            *(__half2*)&Outs[r + 8][c] = v1;
        }
    __syncthreads();

    for (int idx = tid; idx < 128 * 16; idx += 128) {
        int e = idx >> 4, j = idx & 15;
        if (e0 + e < NE)
            *(uint4*)&d_ew[(size_t)(e0 + e) * 4096 + n0 + 8 * j] =
                *(uint4*)&Outs[e][8 * j];
    }
}

// ---------------------------------------------------------------------------
// msg[e] = h[src[e]] @ ew[e]; warp-uniform skip of exact-zero h rows (ReLU
// sparsity) -> ew row reads (128B) skipped, bit-identical math.
// ---------------------------------------------------------------------------
__global__ void k_msg(const int* __restrict__ src,
                      const int* __restrict__ dst) {
    int t  = threadIdx.x;
    int ty = threadIdx.y;
    int e  = blockIdx.x * 8 + ty;
    __shared__ float hs[8][64];
    int s = src[e];
    hs[ty][t]      = d_h[s * 64 + t];
    hs[ty][t + 32] = d_h[s * 64 + t + 32];
    __syncwarp();

    const __half* ewp = d_ew + (size_t)e * 4096 + 2 * t;
    float ax = 0.f, ay = 0.f;
#pragma unroll 8
    for (int i = 0; i < 64; i++) {
        float hv = hs[ty][i];
        if (hv > 0.f) {
            __half2 w = *(const __half2*)(ewp + i * 64);
            float2 wf = __half22float2(w);
            ax += hv * wf.x;
            ay += hv * wf.y;
        }
    }
    int dv = dst[e];
    atomicAdd(&d_agg[dv * 64 + 2 * t],     ax);
    atomicAdd(&d_agg[dv * 64 + 2 * t + 1], ay);
}

// ---------------------------------------------------------------------------
__global__ void k_zero() {
    int i = blockIdx.x * blockDim.x + threadIdx.x;
    if (i < NV * DOUT) d_agg[i] = 0.f;
}

// relu + writeback, re-zero d_agg for the next step (fuses k_zero)
__global__ void k_relu(const float* __restrict__ bias, float* __restrict__ out) {
    int i = blockIdx.x * blockDim.x + threadIdx.x;
    if (i < NV * DOUT) {
        float v = fmaxf(d_agg[i] + bias[i & (DOUT - 1)], 0.f);
        d_agg[i] = 0.f;
        d_h[i] = v;
        if (out) out[i] = v;
    }
}

// ---------------------------------------------------------------------------
extern "C" void kernel_launch(void* const* d_in, const int* in_sizes, int n_in,
                              void* d_out, int out_size) {
    const float* nf   = (const float*)d_in[0];
    const float* ef   = (const float*)d_in[1];
    const int*   src  = (const int*)  d_in[2];
    const int*   dst  = (const int*)  d_in[3];
    const float* Wp   = (const float*)d_in[4];
    const float* bp   = (const float*)d_in[5];
    const float* We1  = (const float*)d_in[6];
    const float* be1  = (const float*)d_in[7];
    const float* We2  = (const float*)d_in[8];
    const float* be2  = (const float*)d_in[9];
    const float* bias = (const float*)d_in[10];
    float* out = (float*)d_out;

    k_project<<<NV, DOUT>>>(nf, Wp, bp);
    k_ehid<<<NE, EHID>>>(ef, We1, be1);
    k_convW<<<(DOUT * DOUT * EHID) / 256, 256>>>(We2);
    k_ew<<<dim3(32, 782), 128>>>(be2);

    k_zero<<<(NV * DOUT) / 256, 256>>>();
    for (int s = 0; s < NSTEPS; s++) {
        k_msg<<<NE / 8, dim3(32, 8)>>>(src, dst);
        k_relu<<<(NV * DOUT) / 256, 256>>>(bias, (s == NSTEPS - 1) ? out : nullptr);
    }
}